// round 9
// baseline (speedup 1.0000x reference)
#include <cuda_runtime.h>

// Analytic collapse of the reference:
//   channel block is affine: y = a*Hadamard2D(x) + b, with
//     a = dot(out_w, conv_w), b = dot(out_w, conv_b) + out_b
//   _H_MAT is symmetric and _H_MAT @ _H_MAT = I, so the double 2-D transform
//   is identity and the constant transforms to H J H^T = 256 * e0 e0^T:
//     out[e] = a*x[e] + 256*b at patch corners (h%256==0 && w%256==0).
// On the float8 index i8 (e = 8*i8): corner iff (i8 & 0xFF1F) == 0, and the
// corner element is the first float of the vector.
//
// R8 experiment: everything 128-bit-based floors at 18.9us with no counter
// saturated. sm_103a has 256-bit global ld/st (LDG.E.256) — halve the
// warp-level memory instruction count per byte to test whether any of the
// residual is per-instruction (LSU dispatch / L1tex replay) overhead rather
// than pure LTS byte rate. Same proven single-wave 1184x256 @ 8 CTA/SM shape.

#ifndef NUM_SMS
#define NUM_SMS 148
#endif
#define CTAS_PER_SM 8
#define BLOCKS  (NUM_SMS * CTAS_PER_SM)  // 1184 = one full resident wave
#define THREADS 256
#define STRIDE  (BLOCKS * THREADS)       // 303,104 float8s
#define N8      (4 * 2048 * 2048 / 8)    // 2,097,152 float8s

__device__ __forceinline__ void ldg256(const float* __restrict__ p,
                                       float4& lo, float4& hi) {
    asm volatile("ld.global.v8.f32 {%0,%1,%2,%3,%4,%5,%6,%7}, [%8];"
                 : "=f"(lo.x), "=f"(lo.y), "=f"(lo.z), "=f"(lo.w),
                   "=f"(hi.x), "=f"(hi.y), "=f"(hi.z), "=f"(hi.w)
                 : "l"(p));
}

__device__ __forceinline__ void stg256(float* __restrict__ p,
                                       const float4& lo, const float4& hi) {
    asm volatile("st.global.v8.f32 [%0], {%1,%2,%3,%4,%5,%6,%7,%8};"
                 :: "l"(p),
                    "f"(lo.x), "f"(lo.y), "f"(lo.z), "f"(lo.w),
                    "f"(hi.x), "f"(hi.y), "f"(hi.z), "f"(hi.w)
                 : "memory");
}

__device__ __forceinline__ void process_slot(const float* __restrict__ in,
                                             float* __restrict__ out,
                                             int i8, float a, float bb) {
    float4 lo, hi;
    ldg256(in + (size_t)i8 * 8, lo, hi);
    lo.x *= a; lo.y *= a; lo.z *= a; lo.w *= a;
    hi.x *= a; hi.y *= a; hi.z *= a; hi.w *= a;
    if ((i8 & 0xFF1F) == 0) {
        lo.x += bb;
    }
    stg256(out + (size_t)i8 * 8, lo, hi);
}

__global__ void __launch_bounds__(THREADS, CTAS_PER_SM)
fused_scale_kernel(const float* __restrict__ in,
                   float* __restrict__ out,
                   const float* __restrict__ conv_w,
                   const float* __restrict__ conv_b,
                   const float* __restrict__ out_w,
                   const float* __restrict__ out_b) {
    const int tid = blockIdx.x * THREADS + threadIdx.x;

    // Scalars, computed redundantly per thread (uniform broadcast loads).
    float a = 0.f, b = 0.f;
#pragma unroll
    for (int c = 0; c < 16; ++c) {
        a += __ldg(&conv_w[c]) * __ldg(&out_w[c]);
        b += __ldg(&conv_b[c]) * __ldg(&out_w[c]);
    }
    const float bb = 256.0f * (b + __ldg(&out_b[0]));

    // 7 slots: 0..5 unconditional (batches of 2 for MLP), slot 6 predicated.
    // Slot 5 max addr: 5*STRIDE + 303,103 = 1,818,623 < N8.  Slot 6 partial.
#pragma unroll
    for (int k = 0; k < 6; k += 2) {
        float4 lo0, hi0, lo1, hi1;
        const int i0 = tid + k * STRIDE;
        const int i1 = tid + (k + 1) * STRIDE;
        ldg256(in + (size_t)i0 * 8, lo0, hi0);
        ldg256(in + (size_t)i1 * 8, lo1, hi1);
        lo0.x *= a; lo0.y *= a; lo0.z *= a; lo0.w *= a;
        hi0.x *= a; hi0.y *= a; hi0.z *= a; hi0.w *= a;
        lo1.x *= a; lo1.y *= a; lo1.z *= a; lo1.w *= a;
        hi1.x *= a; hi1.y *= a; hi1.z *= a; hi1.w *= a;
        if ((i0 & 0xFF1F) == 0) lo0.x += bb;
        if ((i1 & 0xFF1F) == 0) lo1.x += bb;
        stg256(out + (size_t)i0 * 8, lo0, hi0);
        stg256(out + (size_t)i1 * 8, lo1, hi1);
    }
    const int i6 = tid + 6 * STRIDE;
    if (i6 < N8) {
        process_slot(in, out, i6, a, bb);
    }
}

extern "C" void kernel_launch(void* const* d_in, const int* in_sizes, int n_in,
                              void* d_out, int out_size) {
    const float* x      = (const float*)d_in[0];
    const float* conv_w = (const float*)d_in[1];
    const float* conv_b = (const float*)d_in[2];
    const float* out_w  = (const float*)d_in[3];
    const float* out_b  = (const float*)d_in[4];
    float* out = (float*)d_out;

    fused_scale_kernel<<<BLOCKS, THREADS>>>(x, out,
                                            conv_w, conv_b, out_w, out_b);
}